// round 8
// baseline (speedup 1.0000x reference)
#include <cuda_runtime.h>
#include <cuda_bf16.h>
#include <cstdint>

// MXIntGELU: out = mxint_quant(relu(x)) with block (1,32) shared exponent.
//
// The reference's "GELU" reduces exactly to relu:
//   clipped = min(|x|,-beta)+beta = 0  =>  poly = 1  =>  L = sign(x)
//   qout = x*0.5*(1+sign(x)) = relu(x)
// Input quantization is dead code (output never depends on it).
//
// Quantization per 32 contiguous elements v (v >= 0 after relu):
//   m  = max(block_max, 2^-126)
//   e  = floor(log2(m))             (exact via fp32 exponent field)
//   out= min(rint(v * 2^(6-e)), 127) * 2^(e-6)
//
// Layout: 1 thread = 1 float4 per segment; 8 consecutive lanes = one 32-elem
// quant block; block max via 3x shfl_xor (masks 1,2,4 stay in the 8-lane
// group). Each thread handles FOUR float4s from four disjoint quarters
// (front-batched loads -> MLP=4). Pure stream -> .cs hints on load and store.
//
// [R3-R7: held unchanged — broker at capacity every round (8x), zero
//  measurements; 512 MiB stream is the traffic minimum, modeled floor
//  ~73us @ ~7 TB/s. Audited: correctness edge cases (zero blocks, -0.0,
//  half-to-even, clamp 127), graph-capture rules, ALU/SHFL budget vs LTS
//  cap, arbitrary-n robustness. Contingencies await first ncu profile.]

__device__ __forceinline__ float4 quant_block(float4 x)
{
    // relu
    float v0 = fmaxf(x.x, 0.0f);
    float v1 = fmaxf(x.y, 0.0f);
    float v2 = fmaxf(x.z, 0.0f);
    float v3 = fmaxf(x.w, 0.0f);

    // 32-elem block max across the 8-lane group
    float m = fmaxf(fmaxf(v0, v1), fmaxf(v2, v3));
    m = fmaxf(m, __shfl_xor_sync(0xffffffffu, m, 1));
    m = fmaxf(m, __shfl_xor_sync(0xffffffffu, m, 2));
    m = fmaxf(m, __shfl_xor_sync(0xffffffffu, m, 4));

    // e = floor(log2(max(m, 2^-126))) via exponent field (exact for normals)
    m = fmaxf(m, 1.1754943508222875e-38f);   // 2^-126
    int e = (__float_as_int(m) >> 23) - 127; // [-126, 127]

    // scale = 2^(e-6); inv = 2^(6-e), exponent-field construction. Clamps
    // only fire for subnormal-scale blocks (outputs there are ~1e-38 anyway).
    int es = e - 6; if (es < -126) es = -126;
    int ei = 6 - e; if (ei >  127) ei =  127;
    float scale = __int_as_float((es + 127) << 23);
    float inv   = __int_as_float((ei + 127) << 23);

    // v*inv in [0,128); rint can reach 128 on the block max -> clamp at 127.
    // rintf = round-half-to-even, matching jnp.round. v >= 0 so no low clamp.
    float4 r;
    r.x = fminf(rintf(v0 * inv), 127.0f) * scale;
    r.y = fminf(rintf(v1 * inv), 127.0f) * scale;
    r.z = fminf(rintf(v2 * inv), 127.0f) * scale;
    r.w = fminf(rintf(v3 * inv), 127.0f) * scale;
    return r;
}

__global__ void __launch_bounds__(256)
mxint_gelu_kernel(const float4* __restrict__ in,
                  float4* __restrict__ out,
                  int n4, int q4)
{
    int i = blockIdx.x * blockDim.x + threadIdx.x;
    if (i >= q4) return;
    int i1 = i + q4;
    int i2 = i + 2 * q4;
    int i3 = i + 3 * q4;

    // front-batch all four loads (MLP=4), streaming hint (no reuse)
    const float4 z = make_float4(0.f, 0.f, 0.f, 0.f);
    float4 a = __ldcs(&in[i]);
    float4 b = (i1 < n4) ? __ldcs(&in[i1]) : z;
    float4 c = (i2 < n4) ? __ldcs(&in[i2]) : z;
    float4 d = (i3 < n4) ? __ldcs(&in[i3]) : z;

    float4 ra = quant_block(a);
    float4 rb = quant_block(b);
    float4 rc = quant_block(c);
    float4 rd = quant_block(d);

    __stcs(&out[i], ra);
    if (i1 < n4) __stcs(&out[i1], rb);
    if (i2 < n4) __stcs(&out[i2], rc);
    if (i3 < n4) __stcs(&out[i3], rd);
}

extern "C" void kernel_launch(void* const* d_in, const int* in_sizes, int n_in,
                              void* d_out, int out_size)
{
    const float4* in  = (const float4*)d_in[0];
    float4*       out = (float4*)d_out;
    int n  = in_sizes[0];        // 4*4096*4096; divisible by 128
    int n4 = n >> 2;             // float4 count
    int q4 = (n4 + 3) >> 2;      // threads; each does 4 float4

    const int threads = 256;
    int blocks = (q4 + threads - 1) / threads;
    mxint_gelu_kernel<<<blocks, threads>>>(in, out, n4, q4);
}